// round 1
// baseline (speedup 1.0000x reference)
#include <cuda_runtime.h>
#include <cuda_bf16.h>
#include <math_constants.h>

// Problem constants (fixed by the dataset: B=4, N=M=8192, C=3, k=16)
#define BB 4
#define NN 8192
#define MM 8192
#define KK 16
#define TILE 1024
#define BLOCK 64

// Scratch: packed candidate points (x, y, z, |p|^2). 4*8192*16 = 512 KB.
__device__ float4 g_p2[BB * MM];

// ---------------------------------------------------------------------------
// Prep: pack xyz2 into float4 with precomputed squared norm.
// Norm arithmetic mirrors jnp.sum(xyz2**2, -1): (x*x + y*y) + z*z, each op
// individually rounded (no fma contraction).
// ---------------------------------------------------------------------------
__global__ void knn_prep(const float* __restrict__ xyz2) {
    int t = blockIdx.x * blockDim.x + threadIdx.x;
    if (t < BB * MM) {
        float x = xyz2[3 * t + 0];
        float y = xyz2[3 * t + 1];
        float z = xyz2[3 * t + 2];
        float n = __fadd_rn(__fadd_rn(__fmul_rn(x, x), __fmul_rn(y, y)),
                            __fmul_rn(z, z));
        g_p2[t] = make_float4(x, y, z, n);
    }
}

// ---------------------------------------------------------------------------
// Main kernel: one query per thread, warp-broadcast candidate tiles from SMEM.
// Per-thread top-16 kept as an unrolled register-resident sorted list (d2 asc,
// ties resolved naturally since candidate index increases monotonically).
// ---------------------------------------------------------------------------
__global__ void __launch_bounds__(BLOCK) knn_main(const float* __restrict__ xyz1,
                                                  float* __restrict__ out,
                                                  int write_both) {
    __shared__ float4 sm[TILE];

    const int q = blockIdx.x * BLOCK + threadIdx.x;   // global query id in [0, B*N)
    const int b = q >> 13;                            // / NN

    // Query point + norm (same rounding as reference: (x*x + y*y) + z*z)
    const float x = xyz1[3 * q + 0];
    const float y = xyz1[3 * q + 1];
    const float z = xyz1[3 * q + 2];
    const float n1 = __fadd_rn(__fadd_rn(__fmul_rn(x, x), __fmul_rn(y, y)),
                               __fmul_rn(z, z));

    float d[KK];
    int   id[KK];
#pragma unroll
    for (int i = 0; i < KK; ++i) { d[i] = CUDART_INF_F; id[i] = 0; }
    float worst = CUDART_INF_F;

    const float4* __restrict__ src = g_p2 + b * MM;

    for (int t0 = 0; t0 < MM; t0 += TILE) {
        __syncthreads();
        for (int i = threadIdx.x; i < TILE; i += BLOCK)
            sm[i] = src[t0 + i];
        __syncthreads();

#pragma unroll 4
        for (int j = 0; j < TILE; ++j) {
            float4 p = sm[j];                          // broadcast LDS.128
            // dot: fma accumulation chain (gemm-style): fma(z,pz, fma(y,py, x*px))
            float dot = __fmaf_rn(z, p.z, __fmaf_rn(y, p.y, __fmul_rn(x, p.x)));
            // d2 = ((-2*dot) + n1) + n2, each op rounded (reference order)
            float d2 = __fadd_rn(__fadd_rn(__fmul_rn(-2.0f, dot), n1), p.w);

            if (d2 < worst) {
                // shift-insert into sorted list; incoming index is always the
                // largest seen, so strict < on d2 places it after equals
                // (== lower-index-wins tie rule).
                const int ci = t0 + j;
#pragma unroll
                for (int jj = KK - 1; jj > 0; --jj) {
                    bool sh   = d2 < d[jj - 1];
                    bool here = (!sh) && (d2 < d[jj]);
                    float nd  = sh ? d[jj - 1] : (here ? d2 : d[jj]);
                    int   ni  = sh ? id[jj - 1] : (here ? ci : id[jj]);
                    d[jj] = nd; id[jj] = ni;
                }
                if (d2 < d[0]) { d[0] = d2; id[0] = ci; }
                worst = d[KK - 1];
            }
        }
    }

    // Final distances and a stable re-sort by (dist, idx) to repair any
    // sqrt-collision ordering (reference sorts sqrt'd values).
    float dist[KK];
#pragma unroll
    for (int i = 0; i < KK; ++i) dist[i] = __fsqrt_rn(d[i]);

#pragma unroll
    for (int ph = 0; ph < KK; ++ph) {
#pragma unroll
        for (int i = 0; i < KK - 1; ++i) {
            if ((i & 1) == (ph & 1)) {
                bool sw = (dist[i] > dist[i + 1]) ||
                          (dist[i] == dist[i + 1] && id[i] > id[i + 1]);
                float td = sw ? dist[i + 1] : dist[i];
                float tD = sw ? dist[i]     : dist[i + 1];
                int   ti = sw ? id[i + 1]   : id[i];
                int   tI = sw ? id[i]       : id[i + 1];
                dist[i] = td; dist[i + 1] = tD;
                id[i]   = ti; id[i + 1]   = tI;
            }
        }
    }

    const long base = (long)q * KK;
#pragma unroll
    for (int i = 0; i < KK; ++i)
        out[base + i] = dist[i];
    if (write_both) {
        const long off = (long)BB * NN * KK;
#pragma unroll
        for (int i = 0; i < KK; ++i)
            out[off + base + i] = (float)id[i];
    }
}

extern "C" void kernel_launch(void* const* d_in, const int* in_sizes, int n_in,
                              void* d_out, int out_size) {
    const float* xyz1 = (const float*)d_in[0];
    const float* xyz2 = (const float*)d_in[1];
    float* out = (float*)d_out;

    int write_both = (out_size >= 2 * BB * NN * KK) ? 1 : 0;

    knn_prep<<<(BB * MM + 255) / 256, 256>>>(xyz2);
    knn_main<<<(BB * NN) / BLOCK, BLOCK>>>(xyz1, out, write_both);
}